// round 3
// baseline (speedup 1.0000x reference)
#include <cuda_runtime.h>
#include <math.h>

// Problem constants
#define BATCH 2
#define SEQ   2048
#define DMODEL 1024
#define NHEADS 16
#define HDIM  64
#define MROWS (BATCH*SEQ)          // 4096

// ---------------- scratch (device globals; no runtime allocation) -------------
__device__ float g_h  [(size_t)MROWS * DMODEL];        // LN output (reused for LN2)
__device__ float g_qkv[(size_t)MROWS * 3 * DMODEL];    // QKV
__device__ float g_y  [(size_t)MROWS * DMODEL];        // attention output
__device__ float g_x2 [(size_t)MROWS * DMODEL];        // residual after attention
__device__ float g_a  [(size_t)MROWS * 4 * DMODEL];    // MLP hidden

// =============================== LayerNorm ====================================
// one block per row (1024 floats), 256 threads, float4 per thread
__global__ void layernorm_kernel(const float* __restrict__ src,
                                 const float* __restrict__ w,
                                 const float* __restrict__ b,
                                 float* __restrict__ dst) {
    __shared__ float rs[8], rq[8];
    const int row = blockIdx.x;
    const int t   = threadIdx.x;
    const float4 v = ((const float4*)(src + (size_t)row * DMODEL))[t];
    float s = v.x + v.y + v.z + v.w;
    float q = v.x*v.x + v.y*v.y + v.z*v.z + v.w*v.w;
    #pragma unroll
    for (int o = 16; o > 0; o >>= 1) {
        s += __shfl_down_sync(0xffffffffu, s, o);
        q += __shfl_down_sync(0xffffffffu, q, o);
    }
    if ((t & 31) == 0) { rs[t >> 5] = s; rq[t >> 5] = q; }
    __syncthreads();
    if (t == 0) {
        float S = 0.f, Q = 0.f;
        #pragma unroll
        for (int i = 0; i < 8; i++) { S += rs[i]; Q += rq[i]; }
        rs[0] = S; rq[0] = Q;
    }
    __syncthreads();
    const float mean = rs[0] * (1.0f / DMODEL);
    const float var  = rq[0] * (1.0f / DMODEL) - mean * mean;
    const float rstd = rsqrtf(var + 1e-5f);
    const float4 wv = ((const float4*)w)[t];
    const float4 bv = ((const float4*)b)[t];
    float4 o;
    o.x = (v.x - mean) * rstd * wv.x + bv.x;
    o.y = (v.y - mean) * rstd * wv.y + bv.y;
    o.z = (v.z - mean) * rstd * wv.z + bv.z;
    o.w = (v.w - mean) * rstd * wv.w + bv.w;
    ((float4*)(dst + (size_t)row * DMODEL))[t] = o;
}

// ================================ SGEMM =======================================
// C[M,N] = A[M,K] @ B[K,N] + bias (+ epilogue). 128x128 tile, BK=8, 256 thr, 8x8/thr.
// EPI: 0 = none, 1 = add residual res[M,N], 2 = exact GELU
__device__ __forceinline__ float gelu_exact(float x) {
    return 0.5f * x * (1.0f + erff(x * 0.70710678118654752440f));
}

template <int EPI>
__global__ void __launch_bounds__(256, 2)
sgemm_kernel(const float* __restrict__ A, const float* __restrict__ B,
             const float* __restrict__ bias, const float* __restrict__ res,
             float* __restrict__ C, int M, int N, int K) {
    __shared__ float As[8][128];
    __shared__ float Bs[8][128];

    const int tid = threadIdx.x;
    const int bx = blockIdx.x, by = blockIdx.y;

    // global load mapping
    const int rowA = tid >> 1;            // 0..127
    const int colA = (tid & 1) << 2;      // 0 or 4
    const int rowB = tid >> 5;            // 0..7
    const int colB = (tid & 31) << 2;     // 0..124
    const float* Ag = A + (size_t)(by * 128 + rowA) * K + colA;
    const float* Bg = B + (size_t)rowB * N + (size_t)bx * 128 + colB;

    // compute mapping: warps 4x2, lanes 4x8
    const int warp = tid >> 5, lane = tid & 31;
    const int tRow = (warp >> 1) * 32 + (lane >> 3) * 8;   // 0..120
    const int tCol = (warp & 1) * 64 + (lane & 7) * 8;     // 0..120

    float acc[8][8];
    #pragma unroll
    for (int i = 0; i < 8; i++)
        #pragma unroll
        for (int j = 0; j < 8; j++) acc[i][j] = 0.f;

    for (int kt = 0; kt < K; kt += 8) {
        const float4 a4 = *(const float4*)(Ag + kt);
        As[colA + 0][rowA] = a4.x;
        As[colA + 1][rowA] = a4.y;
        As[colA + 2][rowA] = a4.z;
        As[colA + 3][rowA] = a4.w;
        *(float4*)&Bs[rowB][colB] = *(const float4*)(Bg + (size_t)kt * N);
        __syncthreads();
        #pragma unroll
        for (int k = 0; k < 8; k++) {
            float rm[8], rn[8];
            *(float4*)(rm)     = *(const float4*)&As[k][tRow];
            *(float4*)(rm + 4) = *(const float4*)&As[k][tRow + 4];
            *(float4*)(rn)     = *(const float4*)&Bs[k][tCol];
            *(float4*)(rn + 4) = *(const float4*)&Bs[k][tCol + 4];
            #pragma unroll
            for (int i = 0; i < 8; i++)
                #pragma unroll
                for (int j = 0; j < 8; j++)
                    acc[i][j] += rm[i] * rn[j];
        }
        __syncthreads();
    }

    // epilogue
    #pragma unroll
    for (int i = 0; i < 8; i++) {
        const int gr = by * 128 + tRow + i;
        float* Crow = C + (size_t)gr * N + (size_t)bx * 128;
        #pragma unroll
        for (int j = 0; j < 8; j += 4) {
            const int gc = tCol + j;
            const float4 bv = *(const float4*)(bias + (size_t)bx * 128 + gc);
            float4 o;
            o.x = acc[i][j + 0] + bv.x;
            o.y = acc[i][j + 1] + bv.y;
            o.z = acc[i][j + 2] + bv.z;
            o.w = acc[i][j + 3] + bv.w;
            if (EPI == 1) {
                const float4 rv = *(const float4*)(res + (size_t)gr * N + (size_t)bx * 128 + gc);
                o.x += rv.x; o.y += rv.y; o.z += rv.z; o.w += rv.w;
            } else if (EPI == 2) {
                o.x = gelu_exact(o.x); o.y = gelu_exact(o.y);
                o.z = gelu_exact(o.z); o.w = gelu_exact(o.w);
            }
            *(float4*)(Crow + gc) = o;
        }
    }
}

// ============================ Flash attention =================================
// Tq=128, Tk=64, 128 threads (16x8 grid of 8x8 microtiles). fp32 online softmax.
// smem: Qs[d][r] 64x128 | KPs union( Ks[d][c] 64x64 , Ps[k][r] 64x128 ) | Vs[k][d] 64x64
#define ATT_SMEM_BYTES ((8192 + 8192 + 4096) * 4)   // 81920

__global__ void __launch_bounds__(128)
attention_kernel(const float* __restrict__ qkv, float* __restrict__ y) {
    extern __shared__ float sm[];
    float* Qs  = sm;             // 64*128
    float* KPs = sm + 8192;      // 64*64 as K, 64*128 as P
    float* Vs  = sm + 16384;     // 64*64

    const int tid = threadIdx.x;
    const int qt  = blockIdx.x;               // 0..15
    const int bh  = blockIdx.y;               // 0..31
    const int b   = bh >> 4, hh = bh & 15;
    const int q0  = qt * 128;

    const float* qbase = qkv + (size_t)b * SEQ * 3 * DMODEL + hh * HDIM;
    const float* kbase = qbase + DMODEL;
    const float* vbase = qbase + 2 * DMODEL;

    // load Q transposed: Qs[d][r]
    for (int i = tid; i < 128 * 16; i += 128) {
        const int r = i >> 4, c4 = (i & 15) << 2;
        const float4 v4 = *(const float4*)(qbase + (size_t)(q0 + r) * (3 * DMODEL) + c4);
        Qs[(c4 + 0) * 128 + r] = v4.x;
        Qs[(c4 + 1) * 128 + r] = v4.y;
        Qs[(c4 + 2) * 128 + r] = v4.z;
        Qs[(c4 + 3) * 128 + r] = v4.w;
    }

    const int tr = tid >> 3;   // 0..15
    const int tc = tid & 7;    // 0..7

    float O[8][8];
    float mrow[8], lrow[8];
    #pragma unroll
    for (int i = 0; i < 8; i++) {
        mrow[i] = -INFINITY; lrow[i] = 0.f;
        #pragma unroll
        for (int j = 0; j < 8; j++) O[i][j] = 0.f;
    }

    const int nkt = qt * 2 + 2;
    for (int kt = 0; kt < nkt; kt++) {
        const int k0 = kt * 64;
        __syncthreads();   // previous iter done reading KPs/Vs (also covers Q-load on iter 0 path)
        // load K transposed (Ks[d][c]) and V natural (Vs[k][d])
        for (int i = tid; i < 64 * 16; i += 128) {
            const int r = i >> 4, c4 = (i & 15) << 2;
            const float4 k4 = *(const float4*)(kbase + (size_t)(k0 + r) * (3 * DMODEL) + c4);
            KPs[(c4 + 0) * 64 + r] = k4.x;
            KPs[(c4 + 1) * 64 + r] = k4.y;
            KPs[(c4 + 2) * 64 + r] = k4.z;
            KPs[(c4 + 3) * 64 + r] = k4.w;
            const float4 v4 = *(const float4*)(vbase + (size_t)(k0 + r) * (3 * DMODEL) + c4);
            *(float4*)(Vs + r * 64 + c4) = v4;
        }
        __syncthreads();

        // S = Q K^T  (128x64 tile, this thread: rows tr*8.., cols tc*8..)
        float S[8][8];
        #pragma unroll
        for (int i = 0; i < 8; i++)
            #pragma unroll
            for (int j = 0; j < 8; j++) S[i][j] = 0.f;
        #pragma unroll 4
        for (int d = 0; d < 64; d++) {
            float qm[8], kn[8];
            *(float4*)(qm)     = *(const float4*)&Qs[d * 128 + tr * 8];
            *(float4*)(qm + 4) = *(const float4*)&Qs[d * 128 + tr * 8 + 4];
            *(float4*)(kn)     = *(const float4*)&KPs[d * 64 + tc * 8];
            *(float4*)(kn + 4) = *(const float4*)&KPs[d * 64 + tc * 8 + 4];
            #pragma unroll
            for (int i = 0; i < 8; i++)
                #pragma unroll
                for (int j = 0; j < 8; j++)
                    S[i][j] += qm[i] * kn[j];
        }

        // scale + causal mask + online softmax
        const bool domask = (k0 + 64 > q0);
        #pragma unroll
        for (int i = 0; i < 8; i++) {
            const int rg = q0 + tr * 8 + i;
            float mx = -INFINITY;
            #pragma unroll
            for (int j = 0; j < 8; j++) {
                float sv = S[i][j] * 0.125f;   // 1/sqrt(64)
                if (domask && (k0 + tc * 8 + j > rg)) sv = -INFINITY;
                S[i][j] = sv;
                mx = fmaxf(mx, sv);
            }
            #pragma unroll
            for (int o = 1; o < 8; o <<= 1)
                mx = fmaxf(mx, __shfl_xor_sync(0xffffffffu, mx, o));
            const float mnew = fmaxf(mrow[i], mx);
            const float corr = __expf(mrow[i] - mnew);
            float sum = 0.f;
            #pragma unroll
            for (int j = 0; j < 8; j++) {
                const float p = __expf(S[i][j] - mnew);
                S[i][j] = p;
                sum += p;
            }
            #pragma unroll
            for (int o = 1; o < 8; o <<= 1)
                sum += __shfl_xor_sync(0xffffffffu, sum, o);
            lrow[i] = lrow[i] * corr + sum;
            mrow[i] = mnew;
            #pragma unroll
            for (int j = 0; j < 8; j++) O[i][j] *= corr;
        }

        __syncthreads();   // everyone done reading Ks
        // write P transposed: Ps[k][r] = P[r][k]
        #pragma unroll
        for (int j = 0; j < 8; j++)
            #pragma unroll
            for (int i = 0; i < 8; i++)
                KPs[(tc * 8 + j) * 128 + (tr * 8 + i)] = S[i][j];
        __syncthreads();

        // O += P V
        #pragma unroll 4
        for (int k = 0; k < 64; k++) {
            float pm[8], vn[8];
            *(float4*)(pm)     = *(const float4*)&KPs[k * 128 + tr * 8];
            *(float4*)(pm + 4) = *(const float4*)&KPs[k * 128 + tr * 8 + 4];
            *(float4*)(vn)     = *(const float4*)&Vs[k * 64 + tc * 8];
            *(float4*)(vn + 4) = *(const float4*)&Vs[k * 64 + tc * 8 + 4];
            #pragma unroll
            for (int i = 0; i < 8; i++)
                #pragma unroll
                for (int j = 0; j < 8; j++)
                    O[i][j] += pm[i] * vn[j];
        }
    }

    // normalize and store to y[B,T,H*64]
    #pragma unroll
    for (int i = 0; i < 8; i++) {
        const float inv = 1.0f / lrow[i];
        const int t = q0 + tr * 8 + i;
        float* yrow = y + (size_t)(b * SEQ + t) * DMODEL + hh * HDIM + tc * 8;
        #pragma unroll
        for (int j = 0; j < 8; j += 4) {
            float4 o;
            o.x = O[i][j + 0] * inv;
            o.y = O[i][j + 1] * inv;
            o.z = O[i][j + 2] * inv;
            o.w = O[i][j + 3] * inv;
            *(float4*)(yrow + j) = o;
        }
    }
}

// =============================== launcher =====================================
extern "C" void kernel_launch(void* const* d_in, const int* in_sizes, int n_in,
                              void* d_out, int out_size) {
    const float* x      = (const float*)d_in[0];
    const float* ln1_w  = (const float*)d_in[1];
    const float* ln1_b  = (const float*)d_in[2];
    const float* ln2_w  = (const float*)d_in[3];
    const float* ln2_b  = (const float*)d_in[4];
    const float* w_attn = (const float*)d_in[5];
    const float* b_attn = (const float*)d_in[6];
    const float* w_proj = (const float*)d_in[7];
    const float* b_proj = (const float*)d_in[8];
    const float* w_fc   = (const float*)d_in[9];
    const float* b_fc   = (const float*)d_in[10];
    const float* w_fc2  = (const float*)d_in[11];
    const float* b_fc2  = (const float*)d_in[12];
    float* out = (float*)d_out;

    float *h, *qkv, *y, *x2, *a;
    cudaGetSymbolAddress((void**)&h,   g_h);
    cudaGetSymbolAddress((void**)&qkv, g_qkv);
    cudaGetSymbolAddress((void**)&y,   g_y);
    cudaGetSymbolAddress((void**)&x2,  g_x2);
    cudaGetSymbolAddress((void**)&a,   g_a);

    cudaFuncSetAttribute(attention_kernel,
                         cudaFuncAttributeMaxDynamicSharedMemorySize, ATT_SMEM_BYTES);

    // 1) h = LN1(x)
    layernorm_kernel<<<MROWS, 256>>>(x, ln1_w, ln1_b, h);

    // 2) qkv = h @ w_attn + b_attn       [4096,3072] K=1024
    {
        dim3 grid(3 * DMODEL / 128, MROWS / 128);
        sgemm_kernel<0><<<grid, 256>>>(h, w_attn, b_attn, nullptr, qkv,
                                       MROWS, 3 * DMODEL, DMODEL);
    }

    // 3) y = causal_attention(qkv)
    {
        dim3 grid(SEQ / 128, BATCH * NHEADS);
        attention_kernel<<<grid, 128, ATT_SMEM_BYTES>>>(qkv, y);
    }

    // 4) x2 = x + y @ w_proj + b_proj    [4096,1024] K=1024
    {
        dim3 grid(DMODEL / 128, MROWS / 128);
        sgemm_kernel<1><<<grid, 256>>>(y, w_proj, b_proj, x, x2,
                                       MROWS, DMODEL, DMODEL);
    }

    // 5) h = LN2(x2)
    layernorm_kernel<<<MROWS, 256>>>(x2, ln2_w, ln2_b, h);

    // 6) a = gelu(h @ w_fc + b_fc)       [4096,4096] K=1024
    {
        dim3 grid(4 * DMODEL / 128, MROWS / 128);
        sgemm_kernel<2><<<grid, 256>>>(h, w_fc, b_fc, nullptr, a,
                                       MROWS, 4 * DMODEL, DMODEL);
    }

    // 7) out = x2 + a @ w_fc2 + b_fc2    [4096,1024] K=4096
    {
        dim3 grid(DMODEL / 128, MROWS / 128);
        sgemm_kernel<1><<<grid, 256>>>(a, w_fc2, b_fc2, x2, out,
                                       MROWS, DMODEL, 4 * DMODEL);
    }
}

// round 4
// speedup vs baseline: 1.0043x; 1.0043x over previous
#include <cuda_runtime.h>
#include <math.h>

// Problem constants
#define BATCH 2
#define SEQ   2048
#define DMODEL 1024
#define NHEADS 16
#define HDIM  64
#define MROWS (BATCH*SEQ)          // 4096

// ---------------- scratch (device globals; no runtime allocation) -------------
__device__ float g_h  [(size_t)MROWS * DMODEL];        // LN output (reused for LN2)
__device__ float g_qkv[(size_t)MROWS * 3 * DMODEL];    // QKV
__device__ float g_y  [(size_t)MROWS * DMODEL];        // attention output
__device__ float g_x2 [(size_t)MROWS * DMODEL];        // residual after attention
__device__ float g_a  [(size_t)MROWS * 4 * DMODEL];    // MLP hidden

// =============================== LayerNorm ====================================
// one block per row (1024 floats), 256 threads, float4 per thread
__global__ void layernorm_kernel(const float* __restrict__ src,
                                 const float* __restrict__ w,
                                 const float* __restrict__ b,
                                 float* __restrict__ dst) {
    __shared__ float rs[8], rq[8];
    const int row = blockIdx.x;
    const int t   = threadIdx.x;
    const float4 v = ((const float4*)(src + (size_t)row * DMODEL))[t];
    float s = v.x + v.y + v.z + v.w;
    float q = v.x*v.x + v.y*v.y + v.z*v.z + v.w*v.w;
    #pragma unroll
    for (int o = 16; o > 0; o >>= 1) {
        s += __shfl_down_sync(0xffffffffu, s, o);
        q += __shfl_down_sync(0xffffffffu, q, o);
    }
    if ((t & 31) == 0) { rs[t >> 5] = s; rq[t >> 5] = q; }
    __syncthreads();
    if (t == 0) {
        float S = 0.f, Q = 0.f;
        #pragma unroll
        for (int i = 0; i < 8; i++) { S += rs[i]; Q += rq[i]; }
        rs[0] = S; rq[0] = Q;
    }
    __syncthreads();
    const float mean = rs[0] * (1.0f / DMODEL);
    const float var  = rq[0] * (1.0f / DMODEL) - mean * mean;
    const float rstd = rsqrtf(var + 1e-5f);
    const float4 wv = ((const float4*)w)[t];
    const float4 bv = ((const float4*)b)[t];
    float4 o;
    o.x = (v.x - mean) * rstd * wv.x + bv.x;
    o.y = (v.y - mean) * rstd * wv.y + bv.y;
    o.z = (v.z - mean) * rstd * wv.z + bv.z;
    o.w = (v.w - mean) * rstd * wv.w + bv.w;
    ((float4*)(dst + (size_t)row * DMODEL))[t] = o;
}

// ================================ SGEMM =======================================
// C[M,N] = A[M,K] @ B[K,N] + bias (+ epilogue). 128x128 tile, BK=8, 256 thr, 8x8/thr.
// EPI: 0 = none, 1 = add residual res[M,N], 2 = exact GELU
__device__ __forceinline__ float gelu_exact(float x) {
    return 0.5f * x * (1.0f + erff(x * 0.70710678118654752440f));
}

template <int EPI>
__global__ void __launch_bounds__(256, 2)
sgemm_kernel(const float* __restrict__ A, const float* __restrict__ B,
             const float* __restrict__ bias, const float* __restrict__ res,
             float* __restrict__ C, int M, int N, int K) {
    __shared__ float As[8][128];
    __shared__ float Bs[8][128];

    const int tid = threadIdx.x;
    const int bx = blockIdx.x, by = blockIdx.y;

    // global load mapping
    const int rowA = tid >> 1;            // 0..127
    const int colA = (tid & 1) << 2;      // 0 or 4
    const int rowB = tid >> 5;            // 0..7
    const int colB = (tid & 31) << 2;     // 0..124
    const float* Ag = A + (size_t)(by * 128 + rowA) * K + colA;
    const float* Bg = B + (size_t)rowB * N + (size_t)bx * 128 + colB;

    // compute mapping: warps 4x2, lanes 4x8
    const int warp = tid >> 5, lane = tid & 31;
    const int tRow = (warp >> 1) * 32 + (lane >> 3) * 8;   // 0..120
    const int tCol = (warp & 1) * 64 + (lane & 7) * 8;     // 0..120

    float acc[8][8];
    #pragma unroll
    for (int i = 0; i < 8; i++)
        #pragma unroll
        for (int j = 0; j < 8; j++) acc[i][j] = 0.f;

    for (int kt = 0; kt < K; kt += 8) {
        const float4 a4 = *(const float4*)(Ag + kt);
        As[colA + 0][rowA] = a4.x;
        As[colA + 1][rowA] = a4.y;
        As[colA + 2][rowA] = a4.z;
        As[colA + 3][rowA] = a4.w;
        *(float4*)&Bs[rowB][colB] = *(const float4*)(Bg + (size_t)kt * N);
        __syncthreads();
        #pragma unroll
        for (int k = 0; k < 8; k++) {
            float rm[8], rn[8];
            *(float4*)(rm)     = *(const float4*)&As[k][tRow];
            *(float4*)(rm + 4) = *(const float4*)&As[k][tRow + 4];
            *(float4*)(rn)     = *(const float4*)&Bs[k][tCol];
            *(float4*)(rn + 4) = *(const float4*)&Bs[k][tCol + 4];
            #pragma unroll
            for (int i = 0; i < 8; i++)
                #pragma unroll
                for (int j = 0; j < 8; j++)
                    acc[i][j] += rm[i] * rn[j];
        }
        __syncthreads();
    }

    // epilogue
    #pragma unroll
    for (int i = 0; i < 8; i++) {
        const int gr = by * 128 + tRow + i;
        float* Crow = C + (size_t)gr * N + (size_t)bx * 128;
        #pragma unroll
        for (int j = 0; j < 8; j += 4) {
            const int gc = tCol + j;
            const float4 bv = *(const float4*)(bias + (size_t)bx * 128 + gc);
            float4 o;
            o.x = acc[i][j + 0] + bv.x;
            o.y = acc[i][j + 1] + bv.y;
            o.z = acc[i][j + 2] + bv.z;
            o.w = acc[i][j + 3] + bv.w;
            if (EPI == 1) {
                const float4 rv = *(const float4*)(res + (size_t)gr * N + (size_t)bx * 128 + gc);
                o.x += rv.x; o.y += rv.y; o.z += rv.z; o.w += rv.w;
            } else if (EPI == 2) {
                o.x = gelu_exact(o.x); o.y = gelu_exact(o.y);
                o.z = gelu_exact(o.z); o.w = gelu_exact(o.w);
            }
            *(float4*)(Crow + gc) = o;
        }
    }
}

// ============================ Flash attention =================================
// Tq=128, Tk=64, 128 threads (16x8 grid of 8x8 microtiles). fp32 online softmax.
// smem: Qs[d][r] 64x128 | KPs union( Ks[d][c] 64x64 , Ps[k][r] 64x128 ) | Vs[k][d] 64x64
#define ATT_SMEM_BYTES ((8192 + 8192 + 4096) * 4)   // 81920

__global__ void __launch_bounds__(128)
attention_kernel(const float* __restrict__ qkv, float* __restrict__ y) {
    extern __shared__ float sm[];
    float* Qs  = sm;             // 64*128
    float* KPs = sm + 8192;      // 64*64 as K, 64*128 as P
    float* Vs  = sm + 16384;     // 64*64

    const int tid = threadIdx.x;
    const int qt  = blockIdx.x;               // 0..15
    const int bh  = blockIdx.y;               // 0..31
    const int b   = bh >> 4, hh = bh & 15;
    const int q0  = qt * 128;

    const float* qbase = qkv + (size_t)b * SEQ * 3 * DMODEL + hh * HDIM;
    const float* kbase = qbase + DMODEL;
    const float* vbase = qbase + 2 * DMODEL;

    // load Q transposed: Qs[d][r]
    for (int i = tid; i < 128 * 16; i += 128) {
        const int r = i >> 4, c4 = (i & 15) << 2;
        const float4 v4 = *(const float4*)(qbase + (size_t)(q0 + r) * (3 * DMODEL) + c4);
        Qs[(c4 + 0) * 128 + r] = v4.x;
        Qs[(c4 + 1) * 128 + r] = v4.y;
        Qs[(c4 + 2) * 128 + r] = v4.z;
        Qs[(c4 + 3) * 128 + r] = v4.w;
    }

    const int tr = tid >> 3;   // 0..15
    const int tc = tid & 7;    // 0..7

    float O[8][8];
    float mrow[8], lrow[8];
    #pragma unroll
    for (int i = 0; i < 8; i++) {
        mrow[i] = -INFINITY; lrow[i] = 0.f;
        #pragma unroll
        for (int j = 0; j < 8; j++) O[i][j] = 0.f;
    }

    const int nkt = qt * 2 + 2;
    for (int kt = 0; kt < nkt; kt++) {
        const int k0 = kt * 64;
        __syncthreads();   // previous iter done reading KPs/Vs (also covers Q-load on iter 0 path)
        // load K transposed (Ks[d][c]) and V natural (Vs[k][d])
        for (int i = tid; i < 64 * 16; i += 128) {
            const int r = i >> 4, c4 = (i & 15) << 2;
            const float4 k4 = *(const float4*)(kbase + (size_t)(k0 + r) * (3 * DMODEL) + c4);
            KPs[(c4 + 0) * 64 + r] = k4.x;
            KPs[(c4 + 1) * 64 + r] = k4.y;
            KPs[(c4 + 2) * 64 + r] = k4.z;
            KPs[(c4 + 3) * 64 + r] = k4.w;
            const float4 v4 = *(const float4*)(vbase + (size_t)(k0 + r) * (3 * DMODEL) + c4);
            *(float4*)(Vs + r * 64 + c4) = v4;
        }
        __syncthreads();

        // S = Q K^T  (128x64 tile, this thread: rows tr*8.., cols tc*8..)
        float S[8][8];
        #pragma unroll
        for (int i = 0; i < 8; i++)
            #pragma unroll
            for (int j = 0; j < 8; j++) S[i][j] = 0.f;
        #pragma unroll 4
        for (int d = 0; d < 64; d++) {
            float qm[8], kn[8];
            *(float4*)(qm)     = *(const float4*)&Qs[d * 128 + tr * 8];
            *(float4*)(qm + 4) = *(const float4*)&Qs[d * 128 + tr * 8 + 4];
            *(float4*)(kn)     = *(const float4*)&KPs[d * 64 + tc * 8];
            *(float4*)(kn + 4) = *(const float4*)&KPs[d * 64 + tc * 8 + 4];
            #pragma unroll
            for (int i = 0; i < 8; i++)
                #pragma unroll
                for (int j = 0; j < 8; j++)
                    S[i][j] += qm[i] * kn[j];
        }

        // scale + causal mask + online softmax
        const bool domask = (k0 + 64 > q0);
        #pragma unroll
        for (int i = 0; i < 8; i++) {
            const int rg = q0 + tr * 8 + i;
            float mx = -INFINITY;
            #pragma unroll
            for (int j = 0; j < 8; j++) {
                float sv = S[i][j] * 0.125f;   // 1/sqrt(64)
                if (domask && (k0 + tc * 8 + j > rg)) sv = -INFINITY;
                S[i][j] = sv;
                mx = fmaxf(mx, sv);
            }
            #pragma unroll
            for (int o = 1; o < 8; o <<= 1)
                mx = fmaxf(mx, __shfl_xor_sync(0xffffffffu, mx, o));
            const float mnew = fmaxf(mrow[i], mx);
            const float corr = __expf(mrow[i] - mnew);
            float sum = 0.f;
            #pragma unroll
            for (int j = 0; j < 8; j++) {
                const float p = __expf(S[i][j] - mnew);
                S[i][j] = p;
                sum += p;
            }
            #pragma unroll
            for (int o = 1; o < 8; o <<= 1)
                sum += __shfl_xor_sync(0xffffffffu, sum, o);
            lrow[i] = lrow[i] * corr + sum;
            mrow[i] = mnew;
            #pragma unroll
            for (int j = 0; j < 8; j++) O[i][j] *= corr;
        }

        __syncthreads();   // everyone done reading Ks
        // write P transposed: Ps[k][r] = P[r][k]
        #pragma unroll
        for (int j = 0; j < 8; j++)
            #pragma unroll
            for (int i = 0; i < 8; i++)
                KPs[(tc * 8 + j) * 128 + (tr * 8 + i)] = S[i][j];
        __syncthreads();

        // O += P V
        #pragma unroll 4
        for (int k = 0; k < 64; k++) {
            float pm[8], vn[8];
            *(float4*)(pm)     = *(const float4*)&KPs[k * 128 + tr * 8];
            *(float4*)(pm + 4) = *(const float4*)&KPs[k * 128 + tr * 8 + 4];
            *(float4*)(vn)     = *(const float4*)&Vs[k * 64 + tc * 8];
            *(float4*)(vn + 4) = *(const float4*)&Vs[k * 64 + tc * 8 + 4];
            #pragma unroll
            for (int i = 0; i < 8; i++)
                #pragma unroll
                for (int j = 0; j < 8; j++)
                    O[i][j] += pm[i] * vn[j];
        }
    }

    // normalize and store to y[B,T,H*64]
    #pragma unroll
    for (int i = 0; i < 8; i++) {
        const float inv = 1.0f / lrow[i];
        const int t = q0 + tr * 8 + i;
        float* yrow = y + (size_t)(b * SEQ + t) * DMODEL + hh * HDIM + tc * 8;
        #pragma unroll
        for (int j = 0; j < 8; j += 4) {
            float4 o;
            o.x = O[i][j + 0] * inv;
            o.y = O[i][j + 1] * inv;
            o.z = O[i][j + 2] * inv;
            o.w = O[i][j + 3] * inv;
            *(float4*)(yrow + j) = o;
        }
    }
}

// =============================== launcher =====================================
extern "C" void kernel_launch(void* const* d_in, const int* in_sizes, int n_in,
                              void* d_out, int out_size) {
    const float* x      = (const float*)d_in[0];
    const float* ln1_w  = (const float*)d_in[1];
    const float* ln1_b  = (const float*)d_in[2];
    const float* ln2_w  = (const float*)d_in[3];
    const float* ln2_b  = (const float*)d_in[4];
    const float* w_attn = (const float*)d_in[5];
    const float* b_attn = (const float*)d_in[6];
    const float* w_proj = (const float*)d_in[7];
    const float* b_proj = (const float*)d_in[8];
    const float* w_fc   = (const float*)d_in[9];
    const float* b_fc   = (const float*)d_in[10];
    const float* w_fc2  = (const float*)d_in[11];
    const float* b_fc2  = (const float*)d_in[12];
    float* out = (float*)d_out;

    float *h, *qkv, *y, *x2, *a;
    cudaGetSymbolAddress((void**)&h,   g_h);
    cudaGetSymbolAddress((void**)&qkv, g_qkv);
    cudaGetSymbolAddress((void**)&y,   g_y);
    cudaGetSymbolAddress((void**)&x2,  g_x2);
    cudaGetSymbolAddress((void**)&a,   g_a);

    cudaFuncSetAttribute(attention_kernel,
                         cudaFuncAttributeMaxDynamicSharedMemorySize, ATT_SMEM_BYTES);

    // 1) h = LN1(x)
    layernorm_kernel<<<MROWS, 256>>>(x, ln1_w, ln1_b, h);

    // 2) qkv = h @ w_attn + b_attn       [4096,3072] K=1024
    {
        dim3 grid(3 * DMODEL / 128, MROWS / 128);
        sgemm_kernel<0><<<grid, 256>>>(h, w_attn, b_attn, nullptr, qkv,
                                       MROWS, 3 * DMODEL, DMODEL);
    }

    // 3) y = causal_attention(qkv)
    {
        dim3 grid(SEQ / 128, BATCH * NHEADS);
        attention_kernel<<<grid, 128, ATT_SMEM_BYTES>>>(qkv, y);
    }

    // 4) x2 = x + y @ w_proj + b_proj    [4096,1024] K=1024
    {
        dim3 grid(DMODEL / 128, MROWS / 128);
        sgemm_kernel<1><<<grid, 256>>>(y, w_proj, b_proj, x, x2,
                                       MROWS, DMODEL, DMODEL);
    }

    // 5) h = LN2(x2)
    layernorm_kernel<<<MROWS, 256>>>(x2, ln2_w, ln2_b, h);

    // 6) a = gelu(h @ w_fc + b_fc)       [4096,4096] K=1024
    {
        dim3 grid(4 * DMODEL / 128, MROWS / 128);
        sgemm_kernel<2><<<grid, 256>>>(h, w_fc, b_fc, nullptr, a,
                                       MROWS, 4 * DMODEL, DMODEL);
    }

    // 7) out = x2 + a @ w_fc2 + b_fc2    [4096,1024] K=4096
    {
        dim3 grid(DMODEL / 128, MROWS / 128);
        sgemm_kernel<1><<<grid, 256>>>(a, w_fc2, b_fc2, x2, out,
                                       MROWS, DMODEL, 4 * DMODEL);
    }
}

// round 5
// speedup vs baseline: 1.0093x; 1.0050x over previous
#include <cuda_runtime.h>
#include <math.h>

// Problem constants
#define BATCH 2
#define SEQ   2048
#define DMODEL 1024
#define NHEADS 16
#define HDIM  64
#define MROWS (BATCH*SEQ)          // 4096

// ---------------- scratch (device globals; no runtime allocation) -------------
__device__ float g_h  [(size_t)MROWS * DMODEL];        // LN output (reused for LN2)
__device__ float g_qkv[(size_t)MROWS * 3 * DMODEL];    // QKV
__device__ float g_y  [(size_t)MROWS * DMODEL];        // attention output
__device__ float g_x2 [(size_t)MROWS * DMODEL];        // residual after attention
__device__ float g_a  [(size_t)MROWS * 4 * DMODEL];    // MLP hidden

// =============================== LayerNorm ====================================
// one block per row (1024 floats), 256 threads, float4 per thread
__global__ void layernorm_kernel(const float* __restrict__ src,
                                 const float* __restrict__ w,
                                 const float* __restrict__ b,
                                 float* __restrict__ dst) {
    __shared__ float rs[8], rq[8];
    const int row = blockIdx.x;
    const int t   = threadIdx.x;
    const float4 v = ((const float4*)(src + (size_t)row * DMODEL))[t];
    float s = v.x + v.y + v.z + v.w;
    float q = v.x*v.x + v.y*v.y + v.z*v.z + v.w*v.w;
    #pragma unroll
    for (int o = 16; o > 0; o >>= 1) {
        s += __shfl_down_sync(0xffffffffu, s, o);
        q += __shfl_down_sync(0xffffffffu, q, o);
    }
    if ((t & 31) == 0) { rs[t >> 5] = s; rq[t >> 5] = q; }
    __syncthreads();
    if (t == 0) {
        float S = 0.f, Q = 0.f;
        #pragma unroll
        for (int i = 0; i < 8; i++) { S += rs[i]; Q += rq[i]; }
        rs[0] = S; rq[0] = Q;
    }
    __syncthreads();
    const float mean = rs[0] * (1.0f / DMODEL);
    const float var  = rq[0] * (1.0f / DMODEL) - mean * mean;
    const float rstd = rsqrtf(var + 1e-5f);
    const float4 wv = ((const float4*)w)[t];
    const float4 bv = ((const float4*)b)[t];
    float4 o;
    o.x = (v.x - mean) * rstd * wv.x + bv.x;
    o.y = (v.y - mean) * rstd * wv.y + bv.y;
    o.z = (v.z - mean) * rstd * wv.z + bv.z;
    o.w = (v.w - mean) * rstd * wv.w + bv.w;
    ((float4*)(dst + (size_t)row * DMODEL))[t] = o;
}

// ================================ SGEMM =======================================
// C[M,N] = A[M,K] @ B[K,N] + bias (+ epilogue). 128x128 tile, BK=8, 256 thr, 8x8/thr.
// EPI: 0 = none, 1 = add residual res[M,N], 2 = exact GELU
__device__ __forceinline__ float gelu_exact(float x) {
    return 0.5f * x * (1.0f + erff(x * 0.70710678118654752440f));
}

template <int EPI>
__global__ void __launch_bounds__(256, 2)
sgemm_kernel(const float* __restrict__ A, const float* __restrict__ B,
             const float* __restrict__ bias, const float* __restrict__ res,
             float* __restrict__ C, int M, int N, int K) {
    __shared__ float As[8][128];
    __shared__ float Bs[8][128];

    const int tid = threadIdx.x;
    const int bx = blockIdx.x, by = blockIdx.y;

    // global load mapping
    const int rowA = tid >> 1;            // 0..127
    const int colA = (tid & 1) << 2;      // 0 or 4
    const int rowB = tid >> 5;            // 0..7
    const int colB = (tid & 31) << 2;     // 0..124
    const float* Ag = A + (size_t)(by * 128 + rowA) * K + colA;
    const float* Bg = B + (size_t)rowB * N + (size_t)bx * 128 + colB;

    // compute mapping: warps 4x2, lanes 4x8
    const int warp = tid >> 5, lane = tid & 31;
    const int tRow = (warp >> 1) * 32 + (lane >> 3) * 8;   // 0..120
    const int tCol = (warp & 1) * 64 + (lane & 7) * 8;     // 0..120

    float acc[8][8];
    #pragma unroll
    for (int i = 0; i < 8; i++)
        #pragma unroll
        for (int j = 0; j < 8; j++) acc[i][j] = 0.f;

    for (int kt = 0; kt < K; kt += 8) {
        const float4 a4 = *(const float4*)(Ag + kt);
        As[colA + 0][rowA] = a4.x;
        As[colA + 1][rowA] = a4.y;
        As[colA + 2][rowA] = a4.z;
        As[colA + 3][rowA] = a4.w;
        *(float4*)&Bs[rowB][colB] = *(const float4*)(Bg + (size_t)kt * N);
        __syncthreads();
        #pragma unroll
        for (int k = 0; k < 8; k++) {
            float rm[8], rn[8];
            *(float4*)(rm)     = *(const float4*)&As[k][tRow];
            *(float4*)(rm + 4) = *(const float4*)&As[k][tRow + 4];
            *(float4*)(rn)     = *(const float4*)&Bs[k][tCol];
            *(float4*)(rn + 4) = *(const float4*)&Bs[k][tCol + 4];
            #pragma unroll
            for (int i = 0; i < 8; i++)
                #pragma unroll
                for (int j = 0; j < 8; j++)
                    acc[i][j] += rm[i] * rn[j];
        }
        __syncthreads();
    }

    // epilogue
    #pragma unroll
    for (int i = 0; i < 8; i++) {
        const int gr = by * 128 + tRow + i;
        float* Crow = C + (size_t)gr * N + (size_t)bx * 128;
        #pragma unroll
        for (int j = 0; j < 8; j += 4) {
            const int gc = tCol + j;
            const float4 bv = *(const float4*)(bias + (size_t)bx * 128 + gc);
            float4 o;
            o.x = acc[i][j + 0] + bv.x;
            o.y = acc[i][j + 1] + bv.y;
            o.z = acc[i][j + 2] + bv.z;
            o.w = acc[i][j + 3] + bv.w;
            if (EPI == 1) {
                const float4 rv = *(const float4*)(res + (size_t)gr * N + (size_t)bx * 128 + gc);
                o.x += rv.x; o.y += rv.y; o.z += rv.z; o.w += rv.w;
            } else if (EPI == 2) {
                o.x = gelu_exact(o.x); o.y = gelu_exact(o.y);
                o.z = gelu_exact(o.z); o.w = gelu_exact(o.w);
            }
            *(float4*)(Crow + gc) = o;
        }
    }
}

// ============================ Flash attention =================================
// Tq=128, Tk=64, 128 threads (16x8 grid of 8x8 microtiles). fp32 online softmax.
// smem: Qs[d][r] 64x128 | KPs union( Ks[d][c] 64x64 , Ps[k][r] 64x128 ) | Vs[k][d] 64x64
#define ATT_SMEM_BYTES ((8192 + 8192 + 4096) * 4)   // 81920

__global__ void __launch_bounds__(128)
attention_kernel(const float* __restrict__ qkv, float* __restrict__ y) {
    extern __shared__ float sm[];
    float* Qs  = sm;             // 64*128
    float* KPs = sm + 8192;      // 64*64 as K, 64*128 as P
    float* Vs  = sm + 16384;     // 64*64

    const int tid = threadIdx.x;
    const int qt  = blockIdx.x;               // 0..15
    const int bh  = blockIdx.y;               // 0..31
    const int b   = bh >> 4, hh = bh & 15;
    const int q0  = qt * 128;

    const float* qbase = qkv + (size_t)b * SEQ * 3 * DMODEL + hh * HDIM;
    const float* kbase = qbase + DMODEL;
    const float* vbase = qbase + 2 * DMODEL;

    // load Q transposed: Qs[d][r]
    for (int i = tid; i < 128 * 16; i += 128) {
        const int r = i >> 4, c4 = (i & 15) << 2;
        const float4 v4 = *(const float4*)(qbase + (size_t)(q0 + r) * (3 * DMODEL) + c4);
        Qs[(c4 + 0) * 128 + r] = v4.x;
        Qs[(c4 + 1) * 128 + r] = v4.y;
        Qs[(c4 + 2) * 128 + r] = v4.z;
        Qs[(c4 + 3) * 128 + r] = v4.w;
    }

    const int tr = tid >> 3;   // 0..15
    const int tc = tid & 7;    // 0..7

    float O[8][8];
    float mrow[8], lrow[8];
    #pragma unroll
    for (int i = 0; i < 8; i++) {
        mrow[i] = -INFINITY; lrow[i] = 0.f;
        #pragma unroll
        for (int j = 0; j < 8; j++) O[i][j] = 0.f;
    }

    const int nkt = qt * 2 + 2;
    for (int kt = 0; kt < nkt; kt++) {
        const int k0 = kt * 64;
        __syncthreads();   // previous iter done reading KPs/Vs (also covers Q-load on iter 0 path)
        // load K transposed (Ks[d][c]) and V natural (Vs[k][d])
        for (int i = tid; i < 64 * 16; i += 128) {
            const int r = i >> 4, c4 = (i & 15) << 2;
            const float4 k4 = *(const float4*)(kbase + (size_t)(k0 + r) * (3 * DMODEL) + c4);
            KPs[(c4 + 0) * 64 + r] = k4.x;
            KPs[(c4 + 1) * 64 + r] = k4.y;
            KPs[(c4 + 2) * 64 + r] = k4.z;
            KPs[(c4 + 3) * 64 + r] = k4.w;
            const float4 v4 = *(const float4*)(vbase + (size_t)(k0 + r) * (3 * DMODEL) + c4);
            *(float4*)(Vs + r * 64 + c4) = v4;
        }
        __syncthreads();

        // S = Q K^T  (128x64 tile, this thread: rows tr*8.., cols tc*8..)
        float S[8][8];
        #pragma unroll
        for (int i = 0; i < 8; i++)
            #pragma unroll
            for (int j = 0; j < 8; j++) S[i][j] = 0.f;
        #pragma unroll 4
        for (int d = 0; d < 64; d++) {
            float qm[8], kn[8];
            *(float4*)(qm)     = *(const float4*)&Qs[d * 128 + tr * 8];
            *(float4*)(qm + 4) = *(const float4*)&Qs[d * 128 + tr * 8 + 4];
            *(float4*)(kn)     = *(const float4*)&KPs[d * 64 + tc * 8];
            *(float4*)(kn + 4) = *(const float4*)&KPs[d * 64 + tc * 8 + 4];
            #pragma unroll
            for (int i = 0; i < 8; i++)
                #pragma unroll
                for (int j = 0; j < 8; j++)
                    S[i][j] += qm[i] * kn[j];
        }

        // scale + causal mask + online softmax
        const bool domask = (k0 + 64 > q0);
        #pragma unroll
        for (int i = 0; i < 8; i++) {
            const int rg = q0 + tr * 8 + i;
            float mx = -INFINITY;
            #pragma unroll
            for (int j = 0; j < 8; j++) {
                float sv = S[i][j] * 0.125f;   // 1/sqrt(64)
                if (domask && (k0 + tc * 8 + j > rg)) sv = -INFINITY;
                S[i][j] = sv;
                mx = fmaxf(mx, sv);
            }
            #pragma unroll
            for (int o = 1; o < 8; o <<= 1)
                mx = fmaxf(mx, __shfl_xor_sync(0xffffffffu, mx, o));
            const float mnew = fmaxf(mrow[i], mx);
            const float corr = __expf(mrow[i] - mnew);
            float sum = 0.f;
            #pragma unroll
            for (int j = 0; j < 8; j++) {
                const float p = __expf(S[i][j] - mnew);
                S[i][j] = p;
                sum += p;
            }
            #pragma unroll
            for (int o = 1; o < 8; o <<= 1)
                sum += __shfl_xor_sync(0xffffffffu, sum, o);
            lrow[i] = lrow[i] * corr + sum;
            mrow[i] = mnew;
            #pragma unroll
            for (int j = 0; j < 8; j++) O[i][j] *= corr;
        }

        __syncthreads();   // everyone done reading Ks
        // write P transposed: Ps[k][r] = P[r][k]
        #pragma unroll
        for (int j = 0; j < 8; j++)
            #pragma unroll
            for (int i = 0; i < 8; i++)
                KPs[(tc * 8 + j) * 128 + (tr * 8 + i)] = S[i][j];
        __syncthreads();

        // O += P V
        #pragma unroll 4
        for (int k = 0; k < 64; k++) {
            float pm[8], vn[8];
            *(float4*)(pm)     = *(const float4*)&KPs[k * 128 + tr * 8];
            *(float4*)(pm + 4) = *(const float4*)&KPs[k * 128 + tr * 8 + 4];
            *(float4*)(vn)     = *(const float4*)&Vs[k * 64 + tc * 8];
            *(float4*)(vn + 4) = *(const float4*)&Vs[k * 64 + tc * 8 + 4];
            #pragma unroll
            for (int i = 0; i < 8; i++)
                #pragma unroll
                for (int j = 0; j < 8; j++)
                    O[i][j] += pm[i] * vn[j];
        }
    }

    // normalize and store to y[B,T,H*64]
    #pragma unroll
    for (int i = 0; i < 8; i++) {
        const float inv = 1.0f / lrow[i];
        const int t = q0 + tr * 8 + i;
        float* yrow = y + (size_t)(b * SEQ + t) * DMODEL + hh * HDIM + tc * 8;
        #pragma unroll
        for (int j = 0; j < 8; j += 4) {
            float4 o;
            o.x = O[i][j + 0] * inv;
            o.y = O[i][j + 1] * inv;
            o.z = O[i][j + 2] * inv;
            o.w = O[i][j + 3] * inv;
            *(float4*)(yrow + j) = o;
        }
    }
}

// =============================== launcher =====================================
extern "C" void kernel_launch(void* const* d_in, const int* in_sizes, int n_in,
                              void* d_out, int out_size) {
    const float* x      = (const float*)d_in[0];
    const float* ln1_w  = (const float*)d_in[1];
    const float* ln1_b  = (const float*)d_in[2];
    const float* ln2_w  = (const float*)d_in[3];
    const float* ln2_b  = (const float*)d_in[4];
    const float* w_attn = (const float*)d_in[5];
    const float* b_attn = (const float*)d_in[6];
    const float* w_proj = (const float*)d_in[7];
    const float* b_proj = (const float*)d_in[8];
    const float* w_fc   = (const float*)d_in[9];
    const float* b_fc   = (const float*)d_in[10];
    const float* w_fc2  = (const float*)d_in[11];
    const float* b_fc2  = (const float*)d_in[12];
    float* out = (float*)d_out;

    float *h, *qkv, *y, *x2, *a;
    cudaGetSymbolAddress((void**)&h,   g_h);
    cudaGetSymbolAddress((void**)&qkv, g_qkv);
    cudaGetSymbolAddress((void**)&y,   g_y);
    cudaGetSymbolAddress((void**)&x2,  g_x2);
    cudaGetSymbolAddress((void**)&a,   g_a);

    cudaFuncSetAttribute(attention_kernel,
                         cudaFuncAttributeMaxDynamicSharedMemorySize, ATT_SMEM_BYTES);

    // 1) h = LN1(x)
    layernorm_kernel<<<MROWS, 256>>>(x, ln1_w, ln1_b, h);

    // 2) qkv = h @ w_attn + b_attn       [4096,3072] K=1024
    {
        dim3 grid(3 * DMODEL / 128, MROWS / 128);
        sgemm_kernel<0><<<grid, 256>>>(h, w_attn, b_attn, nullptr, qkv,
                                       MROWS, 3 * DMODEL, DMODEL);
    }

    // 3) y = causal_attention(qkv)
    {
        dim3 grid(SEQ / 128, BATCH * NHEADS);
        attention_kernel<<<grid, 128, ATT_SMEM_BYTES>>>(qkv, y);
    }

    // 4) x2 = x + y @ w_proj + b_proj    [4096,1024] K=1024
    {
        dim3 grid(DMODEL / 128, MROWS / 128);
        sgemm_kernel<1><<<grid, 256>>>(y, w_proj, b_proj, x, x2,
                                       MROWS, DMODEL, DMODEL);
    }

    // 5) h = LN2(x2)
    layernorm_kernel<<<MROWS, 256>>>(x2, ln2_w, ln2_b, h);

    // 6) a = gelu(h @ w_fc + b_fc)       [4096,4096] K=1024
    {
        dim3 grid(4 * DMODEL / 128, MROWS / 128);
        sgemm_kernel<2><<<grid, 256>>>(h, w_fc, b_fc, nullptr, a,
                                       MROWS, 4 * DMODEL, DMODEL);
    }

    // 7) out = x2 + a @ w_fc2 + b_fc2    [4096,1024] K=4096
    {
        dim3 grid(DMODEL / 128, MROWS / 128);
        sgemm_kernel<1><<<grid, 256>>>(a, w_fc2, b_fc2, x2, out,
                                       MROWS, DMODEL, 4 * DMODEL);
    }
}